// round 11
// baseline (speedup 1.0000x reference)
#include <cuda_runtime.h>
#include <cuda_fp16.h>
#include <cstdint>

#define TKN 8192   // tokens = 4*2048
#define NF  4096   // in features
#define OF  4096   // out features

// Scratch (static device globals -- allocation-free per harness rules)
__device__ __half g_x[(size_t)TKN * NF];    // 64 MB: fwht(input*SU)*scale, fp16
__device__ __half g_w[(size_t)OF * NF];     // 32 MB: W' = H*W, fp16
__device__ __half g_tmp[(size_t)OF * NF];   // 32 MB: W-FWHT intermediate

// ---------------------------------------------------------------------------
// Kernel 1: g_x = fp16( fwht(input * SU) * Wscale/64 )
// ---------------------------------------------------------------------------
__global__ __launch_bounds__(256) void fwht_in_kernel(
        const float* __restrict__ in, const float* __restrict__ SU,
        const float* __restrict__ wscale) {
    __shared__ float s[4096];
    const int row = blockIdx.x;
    const int tid = threadIdx.x;
    const int lane = tid & 31;

    float v[16];
    const float4* ip = (const float4*)(in + (size_t)row * NF + tid * 16);
    const float4* up = (const float4*)(SU + tid * 16);
    #pragma unroll
    for (int q = 0; q < 4; q++) {
        float4 a = ip[q], b = up[q];
        v[q*4+0] = a.x*b.x; v[q*4+1] = a.y*b.y;
        v[q*4+2] = a.z*b.z; v[q*4+3] = a.w*b.w;
    }

    #pragma unroll
    for (int h = 1; h < 16; h <<= 1)
        #pragma unroll
        for (int i = 0; i < 16; i++)
            if (!(i & h)) {
                float a = v[i], b = v[i ^ h];
                v[i] = a + b; v[i ^ h] = a - b;
            }
    #pragma unroll
    for (int d = 1; d < 16; d <<= 1) {
        #pragma unroll
        for (int r = 0; r < 16; r++) {
            float o = __shfl_xor_sync(0xffffffffu, v[r], d);
            v[r] = (lane & d) ? (o - v[r]) : (v[r] + o);
        }
    }
    float4* sv = (float4*)(s + tid * 16);
    sv[0] = make_float4(v[0], v[1], v[2], v[3]);
    sv[1] = make_float4(v[4], v[5], v[6], v[7]);
    sv[2] = make_float4(v[8], v[9], v[10], v[11]);
    sv[3] = make_float4(v[12], v[13], v[14], v[15]);
    __syncthreads();
    #pragma unroll
    for (int r = 0; r < 16; r++) v[r] = s[r * 256 + tid];
    #pragma unroll
    for (int h = 1; h < 16; h <<= 1)
        #pragma unroll
        for (int i = 0; i < 16; i++)
            if (!(i & h)) {
                float a = v[i], b = v[i ^ h];
                v[i] = a + b; v[i ^ h] = a - b;
            }

    const float sc = wscale[0] * 0.015625f;   // Wscale / sqrt(4096)
    __half* dst = g_x + (size_t)row * NF + tid;
    #pragma unroll
    for (int r = 0; r < 16; r++)
        dst[r * 256] = __float2half_rn(v[r] * sc);
}

// ---------------------------------------------------------------------------
// Kernel 2: fused dequant + FWHT pass 0 over output-dim bits 0..5.
// ---------------------------------------------------------------------------
__global__ __launch_bounds__(256) void wfwht0_kernel(
        const float* __restrict__ cb, const int* __restrict__ qidx) {
    __shared__ float2 scb[512];               // cb: 256 codes x 2 float2
    const int tid = threadIdx.x;
    ((float4*)scb)[tid] = ((const float4*)cb)[tid];   // 256 x 16B = 4KB
    __syncthreads();

    const int b = blockIdx.x;                 // 0..63
    const int col = blockIdx.y * 256 + tid;   // half2 col, 0..2047
    const int qcol = col >> 1;
    const int sub  = col & 1;
    const int* qrow = qidx + (size_t)b * 64 * (NF / 4) + qcol;

    float2 v[64];
    #pragma unroll
    for (int r = 0; r < 64; r++) {
        int q = __ldg(qrow + (size_t)r * (NF / 4));
        v[r] = scb[q * 2 + sub];
    }

    #pragma unroll
    for (int h = 1; h < 64; h <<= 1)
        #pragma unroll
        for (int i = 0; i < 64; i++)
            if (!(i & h)) {
                float2 a = v[i], c = v[i ^ h];
                v[i].x = a.x + c.x;     v[i].y = a.y + c.y;
                v[i ^ h].x = a.x - c.x; v[i ^ h].y = a.y - c.y;
            }

    __half2* d2 = (__half2*)g_tmp;
    const size_t base = (size_t)b * 64 * (NF / 2) + col;
    #pragma unroll
    for (int r = 0; r < 64; r++)
        d2[base + (size_t)r * (NF / 2)] = __float22half2_rn(v[r]);
}

// ---------------------------------------------------------------------------
// Kernel 2b: FWHT pass 1 over output-dim bits 6..11 (rows o = b + 64*r).
// ---------------------------------------------------------------------------
__global__ __launch_bounds__(256) void wfwht1_kernel() {
    const __half2* s2 = (const __half2*)g_tmp;
    __half2*       d2 = (__half2*)g_w;
    const size_t col  = (size_t)blockIdx.y * 256 + threadIdx.x;
    const size_t base = (size_t)blockIdx.x * (NF / 2) + col;
    const size_t rstep = (size_t)64 * (NF / 2);

    float2 v[64];
    #pragma unroll
    for (int r = 0; r < 64; r++)
        v[r] = __half22float2(s2[base + r * rstep]);

    #pragma unroll
    for (int h = 1; h < 64; h <<= 1)
        #pragma unroll
        for (int i = 0; i < 64; i++)
            if (!(i & h)) {
                float2 a = v[i], c = v[i ^ h];
                v[i].x = a.x + c.x;     v[i].y = a.y + c.y;
                v[i ^ h].x = a.x - c.x; v[i ^ h].y = a.y - c.y;
            }

    #pragma unroll
    for (int r = 0; r < 64; r++)
        d2[base + r * rstep] = __float22half2_rn(v[r]);
}

// ---------------------------------------------------------------------------
// Kernel 3: fp16 mma.sync GEMM + fused epilogue, 2 CTAs/SM.
//   out[t][o] = (sum_i g_x[t][i] * g_w[o][i]) * (1/64) * SV[o] + bias[o]
// BM=128 BN=128 BKH=64, 8 warps of 64x32, single-buffered ldmatrix frags
// (4 warps/SMSP hide LDSM latency), 3-stage cp.async pipeline, 96KB smem/CTA
// -> occupancy 2 so one CTA's tensor work covers the other's stage barriers.
// ---------------------------------------------------------------------------
#define BM 128
#define BN 128
#define BKH 64                       // halves per k-stage (128 bytes)
#define STAGES 3
#define KITERS (NF / BKH)            // 64
#define A_TILE_B (BM * 128)          // 16384
#define B_TILE_B (BN * 128)          // 16384
#define STAGE_B  (A_TILE_B + B_TILE_B)      // 32768
#define GEMM_SMEM (STAGES * STAGE_B)        // 98304

__device__ __forceinline__ uint32_t sw128(uint32_t o) { return o ^ ((o >> 3) & 0x70); }

__device__ __forceinline__ void cpa(uint32_t dst, const void* src) {
    asm volatile("cp.async.cg.shared.global [%0], [%1], 16;" :: "r"(dst), "l"(src));
}

__device__ __forceinline__ void ldsm4(uint32_t* r, uint32_t addr) {
    asm volatile("ldmatrix.sync.aligned.m8n8.x4.shared.b16 {%0,%1,%2,%3}, [%4];"
                 : "=r"(r[0]), "=r"(r[1]), "=r"(r[2]), "=r"(r[3]) : "r"(addr));
}

__device__ __forceinline__ void load_stage(uint32_t base, int st, int mBase,
                                           int nBase, int tid) {
    const int k0 = st * BKH;
    const __half* A = g_x + (size_t)mBase * NF + k0;
    const __half* B = g_w + (size_t)nBase * NF + k0;
    #pragma unroll
    for (int i = 0; i < 4; i++) {                 // A: 1024 x 16B
        int id = tid + (i << 8);
        int r = id >> 3, c = id & 7;
        cpa(base + sw128(r * 128 + c * 16), A + (size_t)r * NF + c * 8);
    }
    #pragma unroll
    for (int i = 0; i < 4; i++) {                 // B: 1024 x 16B
        int id = tid + (i << 8);
        int r = id >> 3, c = id & 7;
        cpa(base + A_TILE_B + sw128(r * 128 + c * 16), B + (size_t)r * NF + c * 8);
    }
    asm volatile("cp.async.commit_group;");
}

__global__ __launch_bounds__(256, 2) void gemm_f16_kernel(
        const float* __restrict__ SV, const float* __restrict__ bias,
        float* __restrict__ out) {
    extern __shared__ __align__(1024) uint8_t sm[];
    const uint32_t smem_base = (uint32_t)__cvta_generic_to_shared(sm);

    const int tid  = threadIdx.x;
    const int warp = tid >> 5, lane = tid & 31;
    const int wm = warp >> 2, wn = warp & 3;       // 2 x 4 warp grid, 64x32 tiles
    const int g  = lane >> 2, t = lane & 3;
    const int mBase = blockIdx.y * BM;
    const int nBase = blockIdx.x * BN;

    // ldmatrix lane addressing
    const int a_row  = lane & 15;
    const int a_koff = (lane >> 4) * 16;           // 0/16 bytes
    const int b_row  = (lane & 7) + ((lane >> 4) & 1) * 8;
    const int b_koff = ((lane >> 3) & 1) * 16;

    uint32_t aBase[4], aXor[4], bBase[2], bXor[2];
    #pragma unroll
    for (int mt = 0; mt < 4; mt++) {
        uint32_t rb = (wm * 64 + mt * 16 + a_row) * 128;
        aBase[mt] = rb; aXor[mt] = (rb >> 3) & 0x70;
    }
    #pragma unroll
    for (int np = 0; np < 2; np++) {
        uint32_t rb = (wn * 32 + np * 16 + b_row) * 128;
        bBase[np] = rb; bXor[np] = (rb >> 3) & 0x70;
    }

    float acc[4][4][4];
    #pragma unroll
    for (int a = 0; a < 4; a++)
        #pragma unroll
        for (int b = 0; b < 4; b++)
            #pragma unroll
            for (int c = 0; c < 4; c++) acc[a][b][c] = 0.f;

    // Prologue: stages 0, 1 in flight
    load_stage(smem_base + 0 * STAGE_B, 0, mBase, nBase, tid);
    load_stage(smem_base + 1 * STAGE_B, 1, mBase, nBase, tid);

    for (int s = 0; s < KITERS; s++) {
        // Outstanding groups newer than stage s: 1 while s<KITERS-1, else 0.
        if (s < KITERS - 1)
            asm volatile("cp.async.wait_group 1;" ::: "memory");
        else
            asm volatile("cp.async.wait_group 0;" ::: "memory");
        __syncthreads();

        // Load stage s+2 into buffer (s+2)%3 == (s-1)%3: freed at iter s-1,
        // ordered by the barrier above.
        if (s + 2 < KITERS)
            load_stage(smem_base + ((s + 2) % 3) * STAGE_B, s + 2,
                       mBase, nBase, tid);

        const uint32_t As = smem_base + (s % 3) * STAGE_B;
        const uint32_t Bs = As + A_TILE_B;

        #pragma unroll
        for (int kc = 0; kc < 4; kc++) {           // 4 k-chunks of 16
            const uint32_t ak = kc * 32 + a_koff;
            const uint32_t bk = kc * 32 + b_koff;
            uint32_t af[4][4], bf[2][4];
            #pragma unroll
            for (int mt = 0; mt < 4; mt++)
                ldsm4(af[mt], As + aBase[mt] + (ak ^ aXor[mt]));
            #pragma unroll
            for (int np = 0; np < 2; np++)
                ldsm4(bf[np], Bs + bBase[np] + (bk ^ bXor[np]));
            #pragma unroll
            for (int mt = 0; mt < 4; mt++)
                #pragma unroll
                for (int nt = 0; nt < 4; nt++) {
                    float* c = acc[mt][nt];
                    const uint32_t b0 = bf[nt >> 1][(nt & 1) * 2 + 0];
                    const uint32_t b1 = bf[nt >> 1][(nt & 1) * 2 + 1];
                    asm volatile(
                        "mma.sync.aligned.m16n8k16.row.col.f32.f16.f16.f32 "
                        "{%0,%1,%2,%3}, {%4,%5,%6,%7}, {%8,%9}, {%0,%1,%2,%3};"
                        : "+f"(c[0]), "+f"(c[1]), "+f"(c[2]), "+f"(c[3])
                        : "r"(af[mt][0]), "r"(af[mt][1]),
                          "r"(af[mt][2]), "r"(af[mt][3]),
                          "r"(b0), "r"(b1));
                }
        }
        // no bottom barrier: top barrier of next iter orders compute(s)
        // before the cp.async overwrite of buffer s%3 (issued at iter s+1).
    }

    // Fused epilogue: out = acc/64 * SV + bias
    const float isq = 0.015625f;   // 1/sqrt(4096)
    #pragma unroll
    for (int nt = 0; nt < 4; nt++) {
        const int c0 = nBase + wn * 32 + nt * 8 + (t << 1);
        const float sv0 = __ldg(SV + c0)     * isq;
        const float sv1 = __ldg(SV + c0 + 1) * isq;
        const float bb0 = __ldg(bias + c0);
        const float bb1 = __ldg(bias + c0 + 1);
        #pragma unroll
        for (int mt = 0; mt < 4; mt++) {
            const int r0 = mBase + wm * 64 + mt * 16 + g;
            float* c = acc[mt][nt];
            *(float2*)(out + (size_t)r0 * OF + c0) =
                make_float2(c[0] * sv0 + bb0, c[1] * sv1 + bb1);
            *(float2*)(out + (size_t)(r0 + 8) * OF + c0) =
                make_float2(c[2] * sv0 + bb0, c[3] * sv1 + bb1);
        }
    }
}

// ---------------------------------------------------------------------------
extern "C" void kernel_launch(void* const* d_in, const int* in_sizes, int n_in,
                              void* d_out, int out_size) {
    const float* input  = (const float*)d_in[0];
    const float* SU     = (const float*)d_in[1];
    const float* SV     = (const float*)d_in[2];
    const float* cb     = (const float*)d_in[3];
    const int*   Qidxs  = (const int*)d_in[4];
    const float* Wscale = (const float*)d_in[5];
    const float* bias   = (const float*)d_in[6];
    float* out = (float*)d_out;

    cudaFuncSetAttribute(gemm_f16_kernel,
                         cudaFuncAttributeMaxDynamicSharedMemorySize, GEMM_SMEM);

    fwht_in_kernel<<<TKN, 256>>>(input, SU, Wscale);
    // W' = H * W  (FWHT along output dim; pass 0 fused with codebook dequant)
    wfwht0_kernel<<<dim3(64, NF / 512), 256>>>(cb, Qidxs);
    wfwht1_kernel<<<dim3(64, NF / 512), 256>>>();
    gemm_f16_kernel<<<dim3(OF / BN, TKN / BM), 256, GEMM_SMEM>>>(SV, bias, out);
}

// round 12
// speedup vs baseline: 1.0163x; 1.0163x over previous
#include <cuda_runtime.h>
#include <cuda_fp16.h>
#include <cstdint>

#define TKN 8192   // tokens = 4*2048
#define NF  4096   // in features
#define OF  4096   // out features

// Scratch (static device globals -- allocation-free per harness rules)
__device__ __half g_x[(size_t)TKN * NF];    // 64 MB: fwht(input*SU)*scale, fp16
__device__ __half g_w[(size_t)OF * NF];     // 32 MB: W' = H*W, fp16
__device__ __half g_tmp[(size_t)OF * NF];   // 32 MB: W-FWHT intermediate

// ---------------------------------------------------------------------------
// Kernel 1: g_x = fp16( fwht(input * SU) * Wscale/64 )
// ---------------------------------------------------------------------------
__global__ __launch_bounds__(256) void fwht_in_kernel(
        const float* __restrict__ in, const float* __restrict__ SU,
        const float* __restrict__ wscale) {
    __shared__ float s[4096];
    const int row = blockIdx.x;
    const int tid = threadIdx.x;
    const int lane = tid & 31;

    float v[16];
    const float4* ip = (const float4*)(in + (size_t)row * NF + tid * 16);
    const float4* up = (const float4*)(SU + tid * 16);
    #pragma unroll
    for (int q = 0; q < 4; q++) {
        float4 a = ip[q], b = up[q];
        v[q*4+0] = a.x*b.x; v[q*4+1] = a.y*b.y;
        v[q*4+2] = a.z*b.z; v[q*4+3] = a.w*b.w;
    }

    #pragma unroll
    for (int h = 1; h < 16; h <<= 1)
        #pragma unroll
        for (int i = 0; i < 16; i++)
            if (!(i & h)) {
                float a = v[i], b = v[i ^ h];
                v[i] = a + b; v[i ^ h] = a - b;
            }
    #pragma unroll
    for (int d = 1; d < 16; d <<= 1) {
        #pragma unroll
        for (int r = 0; r < 16; r++) {
            float o = __shfl_xor_sync(0xffffffffu, v[r], d);
            v[r] = (lane & d) ? (o - v[r]) : (v[r] + o);
        }
    }
    float4* sv = (float4*)(s + tid * 16);
    sv[0] = make_float4(v[0], v[1], v[2], v[3]);
    sv[1] = make_float4(v[4], v[5], v[6], v[7]);
    sv[2] = make_float4(v[8], v[9], v[10], v[11]);
    sv[3] = make_float4(v[12], v[13], v[14], v[15]);
    __syncthreads();
    #pragma unroll
    for (int r = 0; r < 16; r++) v[r] = s[r * 256 + tid];
    #pragma unroll
    for (int h = 1; h < 16; h <<= 1)
        #pragma unroll
        for (int i = 0; i < 16; i++)
            if (!(i & h)) {
                float a = v[i], b = v[i ^ h];
                v[i] = a + b; v[i ^ h] = a - b;
            }

    const float sc = wscale[0] * 0.015625f;   // Wscale / sqrt(4096)
    __half* dst = g_x + (size_t)row * NF + tid;
    #pragma unroll
    for (int r = 0; r < 16; r++)
        dst[r * 256] = __float2half_rn(v[r] * sc);
}

// ---------------------------------------------------------------------------
// Kernel 2: fused dequant + FWHT pass 0 over output-dim bits 0..5.
// 128 threads/block, ONE half-lane per thread (64 fp32 regs payload) so
// ~5 CTAs/SM stay resident and the 64 gather loads are latency-hidden.
// Block (b, cby): o-rows [b*64, b*64+64), half-cols [cby*128, cby*128+128).
// ---------------------------------------------------------------------------
__global__ __launch_bounds__(128) void wfwht0_kernel(
        const float* __restrict__ cb, const int* __restrict__ qidx) {
    __shared__ float scb[1024];               // cb: 256 codes x 4 floats = 4KB
    const int tid = threadIdx.x;
    ((float4*)scb)[tid]       = ((const float4*)cb)[tid];
    ((float4*)scb)[tid + 128] = ((const float4*)cb)[tid + 128];
    __syncthreads();

    const int b  = blockIdx.x;                // 0..63
    const int hc = blockIdx.y * 128 + tid;    // half-col (= input index i)
    const int qcol = hc >> 2;                 // code column
    const int sub  = hc & 3;                  // element within code
    const int* qrow = qidx + (size_t)b * 64 * (NF / 4) + qcol;

    float v[64];
    #pragma unroll
    for (int r = 0; r < 64; r++) {
        int q = __ldg(qrow + (size_t)r * (NF / 4));
        v[r] = scb[q * 4 + sub];
    }

    #pragma unroll
    for (int h = 1; h < 64; h <<= 1)
        #pragma unroll
        for (int i = 0; i < 64; i++)
            if (!(i & h)) {
                float a = v[i], c = v[i ^ h];
                v[i] = a + c; v[i ^ h] = a - c;
            }

    __half* d = g_tmp + (size_t)b * 64 * NF + hc;
    #pragma unroll
    for (int r = 0; r < 64; r++)
        d[(size_t)r * NF] = __float2half_rn(v[r]);
}

// ---------------------------------------------------------------------------
// Kernel 2b: FWHT pass 1 over output-dim bits 6..11 (rows o = b + 64*r).
// Same 128-thread / one-half-lane layout.
// ---------------------------------------------------------------------------
__global__ __launch_bounds__(128) void wfwht1_kernel() {
    const int b  = blockIdx.x;                // 0..63
    const int hc = blockIdx.y * 128 + threadIdx.x;
    const __half* s = g_tmp + (size_t)b * NF + hc;
    __half*       d = g_w   + (size_t)b * NF + hc;
    const size_t rstep = (size_t)64 * NF;

    float v[64];
    #pragma unroll
    for (int r = 0; r < 64; r++)
        v[r] = __half2float(__ldg(s + r * rstep));

    #pragma unroll
    for (int h = 1; h < 64; h <<= 1)
        #pragma unroll
        for (int i = 0; i < 64; i++)
            if (!(i & h)) {
                float a = v[i], c = v[i ^ h];
                v[i] = a + c; v[i ^ h] = a - c;
            }

    #pragma unroll
    for (int r = 0; r < 64; r++)
        d[r * rstep] = __float2half_rn(v[r]);
}

// ---------------------------------------------------------------------------
// Kernel 3: fp16 mma.sync GEMM + fused epilogue.  R8 configuration, FROZEN:
// BM=256 BN=128 BKH=128, 2-stage, fragment double-buffering — measured-best
// 613us twice; tensor=74% is the mma.sync dispatch ceiling on sm_103a
// (invariant across occupancy/pipeline variants R8/R9/R11 — do not touch).
// ---------------------------------------------------------------------------
#define BM 256
#define BN 128
#define BKH 128                      // halves per k-stage (256 bytes, 2 sub-tiles)
#define KITERS (NF / BKH)            // 32
#define A_HALF_B (BM * 128)          // 32768
#define B_HALF_B (BN * 128)          // 16384
#define A_TILE_B (2 * A_HALF_B)      // 65536
#define B_TILE_B (2 * B_HALF_B)      // 32768
#define STAGE_B  (A_TILE_B + B_TILE_B)      // 98304
#define GEMM_SMEM (2 * STAGE_B)             // 196608

__device__ __forceinline__ uint32_t sw128(uint32_t o) { return o ^ ((o >> 3) & 0x70); }

__device__ __forceinline__ void cpa(uint32_t dst, const void* src) {
    asm volatile("cp.async.cg.shared.global [%0], [%1], 16;" :: "r"(dst), "l"(src));
}

__device__ __forceinline__ void ldsm4(uint32_t* r, uint32_t addr) {
    asm volatile("ldmatrix.sync.aligned.m8n8.x4.shared.b16 {%0,%1,%2,%3}, [%4];"
                 : "=r"(r[0]), "=r"(r[1]), "=r"(r[2]), "=r"(r[3]) : "r"(addr));
}

__device__ __forceinline__ void load_stage(uint32_t base, int st, int mBase,
                                           int nBase, int tid) {
    const int k0 = st * BKH;
    const __half* A = g_x + (size_t)mBase * NF + k0;
    const __half* B = g_w + (size_t)nBase * NF + k0;
    #pragma unroll
    for (int i = 0; i < 16; i++) {                // A: 4096 x 16B
        int id = tid + (i << 8);
        int r = id >> 4, c16 = id & 15;
        cpa(base + (c16 >> 3) * A_HALF_B + sw128(r * 128 + (c16 & 7) * 16),
            A + (size_t)r * NF + c16 * 8);
    }
    #pragma unroll
    for (int i = 0; i < 8; i++) {                 // B: 2048 x 16B
        int id = tid + (i << 8);
        int r = id >> 4, c16 = id & 15;
        cpa(base + A_TILE_B + (c16 >> 3) * B_HALF_B + sw128(r * 128 + (c16 & 7) * 16),
            B + (size_t)r * NF + c16 * 8);
    }
    asm volatile("cp.async.commit_group;");
}

__global__ __launch_bounds__(256, 1) void gemm_f16_kernel(
        const float* __restrict__ SV, const float* __restrict__ bias,
        float* __restrict__ out) {
    extern __shared__ __align__(1024) uint8_t sm[];
    const uint32_t smem_base = (uint32_t)__cvta_generic_to_shared(sm);

    const int tid  = threadIdx.x;
    const int warp = tid >> 5, lane = tid & 31;
    const int wm = warp >> 1, wn = warp & 1;       // 4 x 2 warp grid, 64x64 tiles
    const int g  = lane >> 2, t = lane & 3;
    const int mBase = blockIdx.y * BM;
    const int nBase = blockIdx.x * BN;

    // ldmatrix lane addressing
    const int a_row  = lane & 15;
    const int a_koff = (lane >> 4) * 16;           // 0/16 bytes
    const int b_row  = (lane & 7) + ((lane >> 4) & 1) * 8;
    const int b_koff = ((lane >> 3) & 1) * 16;

    uint32_t aBase[4], aXor[4], bBase[4], bXor[4];
    #pragma unroll
    for (int mt = 0; mt < 4; mt++) {
        uint32_t rb = (wm * 64 + mt * 16 + a_row) * 128;
        aBase[mt] = rb; aXor[mt] = (rb >> 3) & 0x70;
    }
    #pragma unroll
    for (int np = 0; np < 4; np++) {
        uint32_t rb = (wn * 64 + np * 16 + b_row) * 128;
        bBase[np] = rb; bXor[np] = (rb >> 3) & 0x70;
    }

    float acc[4][8][4];
    #pragma unroll
    for (int a = 0; a < 4; a++)
        #pragma unroll
        for (int b = 0; b < 8; b++)
            #pragma unroll
            for (int c = 0; c < 4; c++) acc[a][b][c] = 0.f;

    load_stage(smem_base, 0, mBase, nBase, tid);

    for (int s = 0; s < KITERS; s++) {
        asm volatile("cp.async.wait_group 0;" ::: "memory");
        __syncthreads();
        if (s + 1 < KITERS)
            load_stage(smem_base + ((s + 1) & 1) * STAGE_B, s + 1,
                       mBase, nBase, tid);

        const uint32_t As = smem_base + (s & 1) * STAGE_B;
        const uint32_t Bs = As + A_TILE_B;

        uint32_t af[2][4][4], bf[2][4][4];
        #pragma unroll
        for (int mt = 0; mt < 4; mt++)
            ldsm4(af[0][mt], As + aBase[mt] + (a_koff ^ aXor[mt]));
        #pragma unroll
        for (int np = 0; np < 4; np++)
            ldsm4(bf[0][np], Bs + bBase[np] + (b_koff ^ bXor[np]));

        #pragma unroll
        for (int kc = 0; kc < 8; kc++) {           // 8 k-chunks of 16
            const int cur = kc & 1, nxt = cur ^ 1;
            if (kc < 7) {
                const int kn = kc + 1;
                const uint32_t ah = As + (kn >> 2) * A_HALF_B;
                const uint32_t bh = Bs + (kn >> 2) * B_HALF_B;
                const uint32_t ak = (kn & 3) * 32 + a_koff;
                const uint32_t bk = (kn & 3) * 32 + b_koff;
                #pragma unroll
                for (int mt = 0; mt < 4; mt++)
                    ldsm4(af[nxt][mt], ah + aBase[mt] + (ak ^ aXor[mt]));
                #pragma unroll
                for (int np = 0; np < 4; np++)
                    ldsm4(bf[nxt][np], bh + bBase[np] + (bk ^ bXor[np]));
            }
            #pragma unroll
            for (int mt = 0; mt < 4; mt++)
                #pragma unroll
                for (int nt = 0; nt < 8; nt++) {
                    float* c = acc[mt][nt];
                    const uint32_t b0 = bf[cur][nt >> 1][(nt & 1) * 2 + 0];
                    const uint32_t b1 = bf[cur][nt >> 1][(nt & 1) * 2 + 1];
                    asm volatile(
                        "mma.sync.aligned.m16n8k16.row.col.f32.f16.f16.f32 "
                        "{%0,%1,%2,%3}, {%4,%5,%6,%7}, {%8,%9}, {%0,%1,%2,%3};"
                        : "+f"(c[0]), "+f"(c[1]), "+f"(c[2]), "+f"(c[3])
                        : "r"(af[cur][mt][0]), "r"(af[cur][mt][1]),
                          "r"(af[cur][mt][2]), "r"(af[cur][mt][3]),
                          "r"(b0), "r"(b1));
                }
        }
        // no bottom barrier: top barrier of next iter orders compute(s)
        // before the cp.async overwrite of buffer s&1 (issued at iter s+1).
    }

    // Fused epilogue: out = acc/64 * SV + bias
    const float isq = 0.015625f;   // 1/sqrt(4096)
    #pragma unroll
    for (int nt = 0; nt < 8; nt++) {
        const int c0 = nBase + wn * 64 + nt * 8 + (t << 1);
        const float sv0 = __ldg(SV + c0)     * isq;
        const float sv1 = __ldg(SV + c0 + 1) * isq;
        const float bb0 = __ldg(bias + c0);
        const float bb1 = __ldg(bias + c0 + 1);
        #pragma unroll
        for (int mt = 0; mt < 4; mt++) {
            const int r0 = mBase + wm * 64 + mt * 16 + g;
            float* c = acc[mt][nt];
            *(float2*)(out + (size_t)r0 * OF + c0) =
                make_float2(c[0] * sv0 + bb0, c[1] * sv1 + bb1);
            *(float2*)(out + (size_t)(r0 + 8) * OF + c0) =
                make_float2(c[2] * sv0 + bb0, c[3] * sv1 + bb1);
        }
    }
}

// ---------------------------------------------------------------------------
extern "C" void kernel_launch(void* const* d_in, const int* in_sizes, int n_in,
                              void* d_out, int out_size) {
    const float* input  = (const float*)d_in[0];
    const float* SU     = (const float*)d_in[1];
    const float* SV     = (const float*)d_in[2];
    const float* cb     = (const float*)d_in[3];
    const int*   Qidxs  = (const int*)d_in[4];
    const float* Wscale = (const float*)d_in[5];
    const float* bias   = (const float*)d_in[6];
    float* out = (float*)d_out;

    cudaFuncSetAttribute(gemm_f16_kernel,
                         cudaFuncAttributeMaxDynamicSharedMemorySize, GEMM_SMEM);

    fwht_in_kernel<<<TKN, 256>>>(input, SU, Wscale);
    // W' = H * W  (FWHT along output dim; pass 0 fused with codebook dequant)
    wfwht0_kernel<<<dim3(64, NF / 128), 128>>>(cb, Qidxs);
    wfwht1_kernel<<<dim3(64, NF / 128), 128>>>();
    gemm_f16_kernel<<<dim3(OF / BN, TKN / BM), 256, GEMM_SMEM>>>(SV, bias, out);
}